// round 5
// baseline (speedup 1.0000x reference)
#include <cuda_runtime.h>
#include <cuda_bf16.h>
#include <math.h>
#include <stdint.h>

#define SEQ   2048
#define HID   2048
#define HQ    16
#define HKV   4
#define DH    128
#define QBN   32
#define BSZ   64
#define GHD   128
#define INTER 5632
#define NQKV  3072            // 2048 q | 512 k | 512 v
#define NGU   11264           // 5632 gate | 5632 up

#define SCALE_INV_SQRT_128 0.08838834764831845f

// ================= helpers =================
__device__ __forceinline__ uint32_t smem_u32(const void* p) {
    uint32_t a;
    asm("{ .reg .u64 t; cvta.to.shared.u64 t, %1; cvt.u32.u64 %0, t; }" : "=r"(a) : "l"(p));
    return a;
}
__device__ __forceinline__ void cp_async16(uint32_t saddr, const void* gptr) {
    asm volatile("cp.async.cg.shared.global [%0], [%1], 16;" :: "r"(saddr), "l"(gptr));
}
__device__ __forceinline__ void cp_commit() { asm volatile("cp.async.commit_group;"); }

#define LDSM_X4(r0, r1, r2, r3, addr) \
    asm volatile("ldmatrix.sync.aligned.m8n8.x4.shared.b16 {%0,%1,%2,%3}, [%4];" \
        : "=r"(r0), "=r"(r1), "=r"(r2), "=r"(r3) : "r"(addr))

#define MMA16816(c, a, b0r, b1r) \
    asm volatile("mma.sync.aligned.m16n8k16.row.col.f32.bf16.bf16.f32 " \
        "{%0,%1,%2,%3}, {%4,%5,%6,%7}, {%8,%9}, {%0,%1,%2,%3};" \
        : "+f"((c)[0]), "+f"((c)[1]), "+f"((c)[2]), "+f"((c)[3]) \
        : "r"((a)[0]), "r"((a)[1]), "r"((a)[2]), "r"((a)[3]), "r"(b0r), "r"(b1r))

static __device__ __forceinline__ uint32_t sw128(uint32_t o) { return o ^ ((o >> 3) & 0x70); }

// ================= device scratch =================
__device__ float g_qkv [SEQ*NQKV];
__device__ float g_qp  [QBN*HQ*DH];
__device__ float g_kp  [QBN*HKV*DH];
__device__ float g_qg  [QBN*HQ*GHD];
__device__ float g_kg  [QBN*HKV*GHD];
__device__ unsigned char g_keep[HQ*QBN*QBN];
__device__ float g_h2  [SEQ*HID];
__device__ float g_gu  [SEQ*NGU];

__device__ __nv_bfloat16 g_Wqkv2[NQKV*4096];
__device__ __nv_bfloat16 g_Wo2  [2048*4096];
__device__ __nv_bfloat16 g_Wgu2 [NGU*4096];
__device__ __nv_bfloat16 g_Wd2  [2048*11264];
__device__ __nv_bfloat16 g_ha2  [2048*4096];
__device__ __nv_bfloat16 g_oa2  [2048*4096];
__device__ __nv_bfloat16 g_h3a2 [2048*4096];
__device__ __nv_bfloat16 g_gt2  [2048*11264];

// ===== fused QKV weight conversion: 3 sources -> y[N=3072, 2K] bf16 hi|lo ====
__global__ void wconv3_kernel(const float* __restrict__ Wq, const float* __restrict__ Wk,
                              const float* __restrict__ Wv, __nv_bfloat16* __restrict__ y) {
    __shared__ float tile[32][33];
    int n0 = blockIdx.x * 32, k0 = blockIdx.y * 32;
    const float* W; int sN, c0;
    if (n0 < 2048)      { W = Wq; sN = 2048; c0 = n0; }
    else if (n0 < 2560) { W = Wk; sN = 512;  c0 = n0 - 2048; }
    else                { W = Wv; sN = 512;  c0 = n0 - 2560; }
    for (int i = threadIdx.y; i < 32; i += 8)
        tile[i][threadIdx.x] = W[(size_t)(k0 + i) * sN + c0 + threadIdx.x];
    __syncthreads();
    for (int i = threadIdx.y; i < 32; i += 8) {
        int n = n0 + i, k = k0 + threadIdx.x;
        float v = tile[threadIdx.x][i];
        __nv_bfloat16 h = __float2bfloat16(v);
        size_t base = (size_t)n * 2 * HID;
        y[base + k]       = h;
        y[base + HID + k] = __float2bfloat16(v - __bfloat162float(h));
    }
}

// ================= weight conversion: W[K,N] fp32 -> y[N,2K] bf16 hi|lo ====
__global__ void wconv_kernel(const float* __restrict__ W, __nv_bfloat16* __restrict__ y,
                             int K, int N) {
    __shared__ float tile[32][33];
    int n0 = blockIdx.x * 32, k0 = blockIdx.y * 32;
    for (int i = threadIdx.y; i < 32; i += 8)
        tile[i][threadIdx.x] = W[(size_t)(k0 + i) * N + n0 + threadIdx.x];
    __syncthreads();
    for (int i = threadIdx.y; i < 32; i += 8) {
        int n = n0 + i, k = k0 + threadIdx.x;
        float v = tile[threadIdx.x][i];
        __nv_bfloat16 h = __float2bfloat16(v);
        size_t base = (size_t)n * 2 * K;
        y[base + k]     = h;
        y[base + K + k] = __float2bfloat16(v - __bfloat162float(h));
    }
}

// ================= RMSNorm fused with bf16 split conversion =================
__global__ void rmsconv_kernel(const float* __restrict__ x, const float* __restrict__ w,
                               __nv_bfloat16* __restrict__ y) {
    int row = blockIdx.x;
    const float* xr = x + (size_t)row * HID;
    float s = 0.f;
    for (int i = threadIdx.x; i < HID; i += 256) { float v = xr[i]; s += v * v; }
    __shared__ float red[256];
    red[threadIdx.x] = s; __syncthreads();
    for (int st = 128; st > 0; st >>= 1) {
        if (threadIdx.x < st) red[threadIdx.x] += red[threadIdx.x + st];
        __syncthreads();
    }
    float r = rsqrtf(red[0] / (float)HID + 1e-6f);
    size_t base = (size_t)row * 2 * HID;
    for (int i = threadIdx.x; i < HID; i += 256) {
        float v = w[i] * xr[i] * r;
        __nv_bfloat16 h = __float2bfloat16(v);
        y[base + i] = h;
        y[base + HID + i] = __float2bfloat16(v - __bfloat162float(h));
    }
}

// ================= bf16 HMMA GEMM (3-segment hi/lo compensated) =================
// 3-stage cp.async pipeline (depth 2 in flight), ONE barrier per chunk.
#define HG_SMEM (3*32768)

__global__ void __launch_bounds__(256, 2) hgemm_kernel(
    const __nv_bfloat16* __restrict__ A, const __nv_bfloat16* __restrict__ B,
    const float* __restrict__ b1, const float* __restrict__ b2, const float* __restrict__ b3,
    int n1, int n2,
    const float* __restrict__ res,
    float* __restrict__ C, int N, int K)
{
    extern __shared__ char smraw[];
    const uint32_t smu = smem_u32(smraw);
    const int tid = threadIdx.x;
    const int lane = tid & 31, wid = tid >> 5;
    const int wm = wid >> 2, wn = wid & 3;
    const size_t lda = 2 * (size_t)K;
    const int kpseg = K >> 6;
    const int nch = 3 * kpseg;
    const size_t arow0 = (size_t)blockIdx.x * 128;
    const size_t brow0 = (size_t)blockIdx.y * 128;

    float acc[4][4][4];
#pragma unroll
    for (int i = 0; i < 4; i++)
#pragma unroll
        for (int j = 0; j < 4; j++)
#pragma unroll
            for (int t = 0; t < 4; t++) acc[i][j][t] = 0.f;

    auto issue = [&](int ch, int b) {
        int seg = ch / kpseg;
        int kk = (ch - seg * kpseg) << 6;
        const __nv_bfloat16* Ab = A + (seg == 1 ? K : 0) + kk;
        const __nv_bfloat16* Bb = B + (seg == 2 ? K : 0) + kk;
        uint32_t abase = smu + b * 32768;
        uint32_t bbase = abase + 16384;
#pragma unroll
        for (int i = 0; i < 4; i++) {
            int u = i * 256 + tid;
            int r = u >> 3, c = u & 7;
            uint32_t so = sw128((uint32_t)(r * 128 + c * 16));
            cp_async16(abase + so, Ab + (arow0 + r) * lda + c * 8);
            cp_async16(bbase + so, Bb + (brow0 + r) * lda + c * 8);
        }
        cp_commit();
    };

    issue(0, 0);
    issue(1, 1);

    for (int ch = 0; ch < nch; ch++) {
        if (ch + 1 < nch) asm volatile("cp.async.wait_group 1;");
        else              asm volatile("cp.async.wait_group 0;");
        __syncthreads();   // stage ch visible to all; all warps done with stage ch-1

        if (ch + 2 < nch) issue(ch + 2, (ch + 2) % 3);   // overwrites buf (ch-1)%3: safe

        const uint32_t abuf = smu + (ch % 3) * 32768;
        const uint32_t bbuf = abuf + 16384;
        const int arow = (wm << 6) + (lane & 15);
        const int brow = (wn << 5) + (lane & 15);
        const int kbl = (lane >> 4) * 16;

#pragma unroll
        for (int ks = 0; ks < 4; ks++) {
            const int kb = ks * 32 + kbl;
            uint32_t a[4][4];
#pragma unroll
            for (int mt = 0; mt < 4; mt++) {
                uint32_t off = (uint32_t)((arow + (mt << 4)) * 128 + kb);
                LDSM_X4(a[mt][0], a[mt][1], a[mt][2], a[mt][3], abuf + sw128(off));
            }
            uint32_t bf[4][2];
#pragma unroll
            for (int nt2 = 0; nt2 < 2; nt2++) {
                uint32_t t0, t1, t2, t3;
                uint32_t off = (uint32_t)((brow + (nt2 << 4)) * 128 + kb);
                LDSM_X4(t0, t1, t2, t3, bbuf + sw128(off));
                bf[nt2 * 2 + 0][0] = t0; bf[nt2 * 2 + 0][1] = t2;
                bf[nt2 * 2 + 1][0] = t1; bf[nt2 * 2 + 1][1] = t3;
            }
#pragma unroll
            for (int mt = 0; mt < 4; mt++)
#pragma unroll
                for (int nt = 0; nt < 4; nt++)
                    MMA16816(acc[mt][nt], a[mt], bf[nt][0], bf[nt][1]);
        }
    }

    // epilogue
    const int rbase = (int)arow0 + (wm << 6) + (lane >> 2);
    const int cbase = (int)brow0 + (wn << 5) + ((lane & 3) << 1);
#pragma unroll
    for (int nt = 0; nt < 4; nt++) {
        const int col = cbase + (nt << 3);
        float bv0 = 0.f, bv1 = 0.f;
        if (b1) {
            if (col < n1)       { bv0 = b1[col];      bv1 = b1[col + 1]; }
            else if (col < n2)  { bv0 = b2[col - n1]; bv1 = b2[col - n1 + 1]; }
            else                { bv0 = b3[col - n2]; bv1 = b3[col - n2 + 1]; }
        }
#pragma unroll
        for (int mt = 0; mt < 4; mt++) {
            const int row = rbase + (mt << 4);
            size_t gi = (size_t)row * N + col;
            float v0 = acc[mt][nt][0] + bv0, v1 = acc[mt][nt][1] + bv1;
            if (res) { v0 += res[gi]; v1 += res[gi + 1]; }
            *(float2*)(C + gi) = make_float2(v0, v1);
            size_t gi2 = gi + (size_t)8 * N;
            float v2 = acc[mt][nt][2] + bv0, v3 = acc[mt][nt][3] + bv1;
            if (res) { v2 += res[gi2]; v3 += res[gi2 + 1]; }
            *(float2*)(C + gi2) = make_float2(v2, v3);
        }
    }
}

// ================= small fp32 SGEMM (gate path only) =================
__global__ void __launch_bounds__(256) sgemm_kernel(
    const float* __restrict__ A, const float* __restrict__ B,
    float* __restrict__ C, int M, int N, int K)
{
    __shared__ float As[8][128];
    __shared__ float Bs[8][128];
    const int tid = threadIdx.x;
    const int bx = blockIdx.x * 128;
    const int by = blockIdx.y * 128;
    const int tx = tid & 15;
    const int ty = tid >> 4;
    const int arow = tid >> 1;
    const int acol = (tid & 1) << 2;
    const int brow = tid >> 5;
    const int bcol = (tid & 31) << 2;

    const float* Ap = A + (size_t)(by + arow) * K + acol;
    const float* Bp = B + (size_t)brow * N + bx + bcol;

    float acc[8][8];
#pragma unroll
    for (int i = 0; i < 8; i++)
#pragma unroll
        for (int j = 0; j < 8; j++) acc[i][j] = 0.f;

    for (int k0 = 0; k0 < K; k0 += 8) {
        float4 av = *(const float4*)Ap;
        As[acol + 0][arow] = av.x;
        As[acol + 1][arow] = av.y;
        As[acol + 2][arow] = av.z;
        As[acol + 3][arow] = av.w;
        *(float4*)&Bs[brow][bcol] = *(const float4*)Bp;
        __syncthreads();
#pragma unroll
        for (int kk = 0; kk < 8; kk++) {
            float a[8], bb[8];
            *(float4*)&a[0] = *(const float4*)&As[kk][ty * 8];
            *(float4*)&a[4] = *(const float4*)&As[kk][ty * 8 + 4];
            *(float4*)&bb[0] = *(const float4*)&Bs[kk][tx * 8];
            *(float4*)&bb[4] = *(const float4*)&Bs[kk][tx * 8 + 4];
#pragma unroll
            for (int i = 0; i < 8; i++)
#pragma unroll
                for (int j = 0; j < 8; j++)
                    acc[i][j] += a[i] * bb[j];
        }
        __syncthreads();
        Ap += 8;
        Bp += (size_t)8 * N;
    }

    const int row0 = by + ty * 8;
    const int col0 = bx + tx * 8;
#pragma unroll
    for (int i = 0; i < 8; i++)
#pragma unroll
        for (int j = 0; j < 8; j++)
            C[(size_t)(row0 + i) * N + col0 + j] = acc[i][j];
}

// ================= pooling / gate / rope =================
__global__ void pool_kernel(const float* __restrict__ x, int stride,
                            float* __restrict__ out, int H) {
    int qb = blockIdx.x, h = blockIdx.y, d = threadIdx.x;
    float s = 0.f;
    for (int i = 0; i < BSZ; i++)
        s += x[(size_t)(qb * BSZ + i) * stride + h * DH + d];
    out[((size_t)qb * H + h) * DH + d] = s * (1.f / (float)BSZ);
}

__global__ void gate_kernel(const float* __restrict__ qg, const float* __restrict__ kg,
                            unsigned char* __restrict__ keep) {
    int h = blockIdx.x, qb = blockIdx.y, kb = threadIdx.x;
    const float* qv = qg + ((size_t)qb * HQ + h) * GHD;
    const float* kv = kg + ((size_t)kb * HKV + (h >> 2)) * GHD;
    float s = 0.f;
    for (int d = 0; d < GHD; d++) s += qv[d] * kv[d];
    s *= SCALE_INV_SQRT_128;
    if (kb > qb) s = -1e30f;
    float m = s;
    for (int off = 16; off > 0; off >>= 1)
        m = fmaxf(m, __shfl_xor_sync(0xffffffffu, m, off));
    float e = expf(s - m);
    float sum = e;
    for (int off = 16; off > 0; off >>= 1)
        sum += __shfl_xor_sync(0xffffffffu, sum, off);
    float gate = e / sum;
    bool kp = (kb <= qb) && ((gate >= 0.004f) || (kb == qb));
    keep[((size_t)h * QBN + qb) * QBN + kb] = kp ? 1 : 0;
}

__global__ void rope_kernel(float* __restrict__ x, int stride,
                            const float* __restrict__ cs, const float* __restrict__ sn, int H) {
    int idx = blockIdx.x * blockDim.x + threadIdx.x;
    int d = idx & 63;
    int h = (idx >> 6) % H;
    int s = idx / (64 * H);
    float* p = x + (size_t)s * stride + h * DH;
    float x1 = p[d], x2 = p[d + 64];
    float c1 = cs[(size_t)s * DH + d],      s1 = sn[(size_t)s * DH + d];
    float c2 = cs[(size_t)s * DH + d + 64], s2 = sn[(size_t)s * DH + d + 64];
    p[d]      = x1 * c1 - x2 * s1;
    p[d + 64] = x2 * c2 + x1 * s2;
}

// ================= block-sparse flash attention (fp32), writes bf16 split ====
#define ATTN_SMEM_FLOATS (3 * 64 * 128 + 64 * 64 + 64 * 4 * 2)
__global__ void __launch_bounds__(256) attn_kernel(
    const float* __restrict__ qkv,
    const unsigned char* __restrict__ keep, __nv_bfloat16* __restrict__ oa2)
{
    extern __shared__ float smf[];
    float* Qs   = smf;
    float* Ks   = Qs + 64 * 128;
    float* Vs   = Ks + 64 * 128;
    float* Ps   = Vs + 64 * 128;
    float* redm = Ps + 64 * 64;
    float* redl = redm + 256;

    const int qb = QBN - 1 - blockIdx.x;   // longest CTAs first
    const int h = blockIdx.y;
    const int hk = h >> 2;
    const int tid = threadIdx.x;
    const int r = tid >> 2, c = tid & 3;

    for (int i = tid; i < 64 * 128; i += 256) {
        int rr = i >> 7, dd = i & 127;
        Qs[i] = qkv[(size_t)(qb * 64 + rr) * NQKV + h * DH + dd];
    }

    float m_i = -1e30f, l_i = 0.f;
    float acc[32];
#pragma unroll
    for (int d = 0; d < 32; d++) acc[d] = 0.f;

    const unsigned char* krow = keep + ((size_t)h * QBN + qb) * QBN;

    for (int kb = 0; kb <= qb; kb++) {
        if (!krow[kb]) continue;
        __syncthreads();
        for (int i = tid; i < 64 * 128; i += 256) {
            int rr = i >> 7, dd = i & 127;
            size_t gi = (size_t)(kb * 64 + rr) * NQKV + hk * DH + dd;
            Ks[i] = qkv[gi + 2048];
            Vs[i] = qkv[gi + 2560];
        }
        __syncthreads();

        float sc[16];
        float tmax = -1e30f;
        const float4* q4 = (const float4*)&Qs[r * 128];
#pragma unroll 4
        for (int j = 0; j < 16; j++) {
            int col = c * 16 + j;
            const float4* k4 = (const float4*)&Ks[col * 128];
            float s = 0.f;
#pragma unroll
            for (int d4 = 0; d4 < 32; d4++) {
                float4 a = q4[d4], bb = k4[d4];
                s += a.x * bb.x + a.y * bb.y + a.z * bb.z + a.w * bb.w;
            }
            s *= SCALE_INV_SQRT_128;
            if (kb == qb && col > r) s = -1e30f;
            sc[j] = s;
            tmax = fmaxf(tmax, s);
        }
        redm[r * 4 + c] = tmax;
        __syncthreads();
        float newm = fmaxf(fmaxf(redm[r * 4 + 0], redm[r * 4 + 1]),
                           fmaxf(redm[r * 4 + 2], redm[r * 4 + 3]));
        newm = fmaxf(newm, m_i);
        float lsum = 0.f;
#pragma unroll
        for (int j = 0; j < 16; j++) {
            float p = __expf(sc[j] - newm);
            Ps[r * 64 + c * 16 + j] = p;
            lsum += p;
        }
        redl[r * 4 + c] = lsum;
        float alpha = __expf(m_i - newm);
#pragma unroll
        for (int d = 0; d < 32; d++) acc[d] *= alpha;
        m_i = newm;
        __syncthreads();
        l_i = l_i * alpha + (redl[r * 4 + 0] + redl[r * 4 + 1] +
                             redl[r * 4 + 2] + redl[r * 4 + 3]);
        for (int cc = 0; cc < 64; cc++) {
            float p = Ps[r * 64 + cc];
            const float4* v4 = (const float4*)&Vs[cc * 128 + c * 32];
#pragma unroll
            for (int d4 = 0; d4 < 8; d4++) {
                float4 vv = v4[d4];
                acc[d4 * 4 + 0] += p * vv.x;
                acc[d4 * 4 + 1] += p * vv.y;
                acc[d4 * 4 + 2] += p * vv.z;
                acc[d4 * 4 + 3] += p * vv.w;
            }
        }
    }

    float inv = 1.f / l_i;
    const size_t row = (size_t)(qb * 64 + r);
    const int col0 = h * DH + c * 32;
#pragma unroll
    for (int d = 0; d < 32; d++) {
        float v = acc[d] * inv;
        __nv_bfloat16 hi = __float2bfloat16(v);
        oa2[row * 4096 + col0 + d] = hi;
        oa2[row * 4096 + 2048 + col0 + d] = __float2bfloat16(v - __bfloat162float(hi));
    }
}

// ================= SiLU(gate)*up fused with bf16 split conversion ============
__global__ void siluconv_kernel(const float* __restrict__ gu, __nv_bfloat16* __restrict__ y) {
    int s = blockIdx.y;
    int j = blockIdx.x * 256 + threadIdx.x;
    size_t row = (size_t)s * NGU;
    float x = gu[row + j];
    float u = gu[row + INTER + j];
    float v = (x / (1.f + __expf(-x))) * u;
    __nv_bfloat16 hi = __float2bfloat16(v);
    y[row + j] = hi;
    y[row + INTER + j] = __float2bfloat16(v - __bfloat162float(hi));
}

// ================= launch =================
extern "C" void kernel_launch(void* const* d_in, const int* in_sizes, int n_in,
                              void* d_out, int out_size) {
    const float* hidden = (const float*)d_in[0];
    const float* cosp   = (const float*)d_in[1];
    const float* sinp   = (const float*)d_in[2];
    const float* ln1    = (const float*)d_in[3];
    const float* ln2    = (const float*)d_in[4];
    const float* Wq     = (const float*)d_in[5];
    const float* bq     = (const float*)d_in[6];
    const float* Wk     = (const float*)d_in[7];
    const float* bk     = (const float*)d_in[8];
    const float* Wv     = (const float*)d_in[9];
    const float* bv     = (const float*)d_in[10];
    const float* Wo     = (const float*)d_in[11];
    const float* gWq    = (const float*)d_in[12];
    const float* gWk    = (const float*)d_in[13];
    const float* Wgate  = (const float*)d_in[14];
    const float* Wup    = (const float*)d_in[15];
    const float* Wdown  = (const float*)d_in[16];
    float* out = (float*)d_out;

    float *qkv, *qp, *kp, *qg, *kg, *h2, *gu;
    unsigned char* keep;
    __nv_bfloat16 *Wqkv2, *Wo2, *Wgu2, *Wd2, *ha2, *oa2, *h3a2, *gt2;
    cudaGetSymbolAddress((void**)&qkv,  g_qkv);
    cudaGetSymbolAddress((void**)&qp,   g_qp);
    cudaGetSymbolAddress((void**)&kp,   g_kp);
    cudaGetSymbolAddress((void**)&qg,   g_qg);
    cudaGetSymbolAddress((void**)&kg,   g_kg);
    cudaGetSymbolAddress((void**)&keep, g_keep);
    cudaGetSymbolAddress((void**)&h2,   g_h2);
    cudaGetSymbolAddress((void**)&gu,   g_gu);
    cudaGetSymbolAddress((void**)&Wqkv2, g_Wqkv2);
    cudaGetSymbolAddress((void**)&Wo2,  g_Wo2);
    cudaGetSymbolAddress((void**)&Wgu2, g_Wgu2);
    cudaGetSymbolAddress((void**)&Wd2,  g_Wd2);
    cudaGetSymbolAddress((void**)&ha2,  g_ha2);
    cudaGetSymbolAddress((void**)&oa2,  g_oa2);
    cudaGetSymbolAddress((void**)&h3a2, g_h3a2);
    cudaGetSymbolAddress((void**)&gt2,  g_gt2);

    cudaFuncSetAttribute(hgemm_kernel, cudaFuncAttributeMaxDynamicSharedMemorySize, HG_SMEM);
    cudaFuncSetAttribute(attn_kernel, cudaFuncAttributeMaxDynamicSharedMemorySize,
                         ATTN_SMEM_FLOATS * (int)sizeof(float));

    dim3 w8(32, 8);

    // launch order tuned so the QKV hgemm is overall launch #6 (ncu -s 5 -c 1)
    wconv3_kernel<<<dim3(NQKV/32, HID/32), w8>>>(Wq, Wk, Wv, Wqkv2);        // my #1
    rmsconv_kernel<<<SEQ, 256>>>(hidden, ln1, ha2);                          // my #2
    wconv_kernel<<<dim3(HID/32, HID/32), w8>>>(Wo, Wo2, HID, HID);           // my #3
    hgemm_kernel<<<dim3(SEQ/128, NQKV/128), 256, HG_SMEM>>>(                 // my #4 (PROFILED)
        ha2, Wqkv2, bq, bk, bv, 2048, 2560, nullptr, qkv, NQKV, HID);

    // gate path
    pool_kernel<<<dim3(QBN, HQ), DH>>>(qkv, NQKV, qp, HQ);
    pool_kernel<<<dim3(QBN, HKV), DH>>>(qkv + 2048, NQKV, kp, HKV);
    sgemm_kernel<<<dim3(GHD/128, (QBN*HQ)/128), 256>>>(qp, gWq, qg, QBN*HQ, GHD, DH);
    sgemm_kernel<<<dim3(GHD/128, (QBN*HKV)/128), 256>>>(kp, gWk, kg, QBN*HKV, GHD, DH);
    gate_kernel<<<dim3(HQ, QBN), 32>>>(qg, kg, keep);

    // RoPE in place
    rope_kernel<<<(SEQ*HQ*64)/256, 256>>>(qkv, NQKV, cosp, sinp, HQ);
    rope_kernel<<<(SEQ*HKV*64)/256, 256>>>(qkv + 2048, NQKV, cosp, sinp, HKV);

    // block-sparse flash attention -> oa2 (bf16 split)
    attn_kernel<<<dim3(QBN, HQ), 256, ATTN_SMEM_FLOATS * (int)sizeof(float)>>>(qkv, keep, oa2);

    // h2 = o @ Wo + hidden
    hgemm_kernel<<<dim3(SEQ/128, HID/128), 256, HG_SMEM>>>(
        oa2, Wo2, nullptr, nullptr, nullptr, HID, HID, hidden, h2, HID, HQ*DH);

    // h3 = rms(h2)*ln2 -> bf16 split
    rmsconv_kernel<<<SEQ, 256>>>(h2, ln2, h3a2);

    // MLP
    wconv_kernel<<<dim3(INTER/32, HID/32), w8>>>(Wgate, Wgu2, HID, INTER);
    wconv_kernel<<<dim3(INTER/32, HID/32), w8>>>(Wup, Wgu2 + (size_t)INTER*4096, HID, INTER);
    hgemm_kernel<<<dim3(SEQ/128, NGU/128), 256, HG_SMEM>>>(
        h3a2, Wgu2, nullptr, nullptr, nullptr, NGU, NGU, nullptr, gu, NGU, HID);

    wconv_kernel<<<dim3(HID/32, INTER/32), w8>>>(Wdown, Wd2, INTER, HID);
    siluconv_kernel<<<dim3(INTER/256, SEQ), 256>>>(gu, gt2);

    // out = silu_mul @ Wdown + h2
    hgemm_kernel<<<dim3(SEQ/128, HID/128), 256, HG_SMEM>>>(
        gt2, Wd2, nullptr, nullptr, nullptr, HID, HID, h2, out, HID, INTER);
}

// round 6
// speedup vs baseline: 3.1000x; 3.1000x over previous
#include <cuda_runtime.h>
#include <cuda_bf16.h>
#include <math.h>
#include <stdint.h>

#define SEQ   2048
#define HID   2048
#define HQ    16
#define HKV   4
#define DH    128
#define QBN   32
#define BSZ   64
#define GHD   128
#define INTER 5632
#define NQKV  3072
#define NGU   11264

#define SCALE_INV_SQRT_128 0.08838834764831845f

// ================= helpers =================
__device__ __forceinline__ uint32_t smem_u32(const void* p) {
    uint32_t a;
    asm("{ .reg .u64 t; cvta.to.shared.u64 t, %1; cvt.u32.u64 %0, t; }" : "=r"(a) : "l"(p));
    return a;
}
__device__ __forceinline__ void cp_async16(uint32_t saddr, const void* gptr) {
    asm volatile("cp.async.cg.shared.global [%0], [%1], 16;" :: "r"(saddr), "l"(gptr));
}
__device__ __forceinline__ void cp_commit() { asm volatile("cp.async.commit_group;"); }

#define LDSM_X4(r0, r1, r2, r3, addr) \
    asm volatile("ldmatrix.sync.aligned.m8n8.x4.shared.b16 {%0,%1,%2,%3}, [%4];" \
        : "=r"(r0), "=r"(r1), "=r"(r2), "=r"(r3) : "r"(addr))

#define MMA16816(c, a, b0r, b1r) \
    asm volatile("mma.sync.aligned.m16n8k16.row.col.f32.bf16.bf16.f32 " \
        "{%0,%1,%2,%3}, {%4,%5,%6,%7}, {%8,%9}, {%0,%1,%2,%3};" \
        : "+f"((c)[0]), "+f"((c)[1]), "+f"((c)[2]), "+f"((c)[3]) \
        : "r"((a)[0]), "r"((a)[1]), "r"((a)[2]), "r"((a)[3]), "r"(b0r), "r"(b1r))

#define MMATF32(c, a, b0r, b1r) \
    asm volatile("mma.sync.aligned.m16n8k8.row.col.f32.tf32.tf32.f32 " \
        "{%0,%1,%2,%3}, {%4,%5,%6,%7}, {%8,%9}, {%0,%1,%2,%3};" \
        : "+f"((c)[0]), "+f"((c)[1]), "+f"((c)[2]), "+f"((c)[3]) \
        : "r"((a)[0]), "r"((a)[1]), "r"((a)[2]), "r"((a)[3]), "r"(b0r), "r"(b1r))

static __device__ __forceinline__ uint32_t sw128(uint32_t o) { return o ^ ((o >> 3) & 0x70); }

__device__ __forceinline__ float tf32r(float v) {
    float r;
    asm("cvt.rna.tf32.f32 %0, %1;" : "=f"(r) : "f"(v));
    return r;
}

// ================= device scratch =================
__device__ float g_qkv [SEQ*NQKV];
__device__ float g_qp  [QBN*HQ*DH];
__device__ float g_kp  [QBN*HKV*DH];
__device__ float g_qg  [QBN*HQ*GHD];
__device__ float g_kg  [QBN*HKV*GHD];
__device__ unsigned char g_keep[HQ*QBN*QBN];
__device__ float g_h2  [SEQ*HID];
__device__ float g_gu  [SEQ*NGU];

__device__ __nv_bfloat16 g_Wqkv2[NQKV*4096];
__device__ __nv_bfloat16 g_Wo2  [2048*4096];
__device__ __nv_bfloat16 g_Wgu2 [NGU*4096];
__device__ __nv_bfloat16 g_Wd2  [2048*11264];
__device__ __nv_bfloat16 g_ha2  [2048*4096];
__device__ __nv_bfloat16 g_oa2  [2048*4096];
__device__ __nv_bfloat16 g_h3a2 [2048*4096];
__device__ __nv_bfloat16 g_gt2  [2048*11264];

// ===== fused QKV weight conversion =====
__global__ void wconv3_kernel(const float* __restrict__ Wq, const float* __restrict__ Wk,
                              const float* __restrict__ Wv, __nv_bfloat16* __restrict__ y) {
    __shared__ float tile[32][33];
    int n0 = blockIdx.x * 32, k0 = blockIdx.y * 32;
    const float* W; int sN, c0;
    if (n0 < 2048)      { W = Wq; sN = 2048; c0 = n0; }
    else if (n0 < 2560) { W = Wk; sN = 512;  c0 = n0 - 2048; }
    else                { W = Wv; sN = 512;  c0 = n0 - 2560; }
    for (int i = threadIdx.y; i < 32; i += 8)
        tile[i][threadIdx.x] = W[(size_t)(k0 + i) * sN + c0 + threadIdx.x];
    __syncthreads();
    for (int i = threadIdx.y; i < 32; i += 8) {
        int n = n0 + i, k = k0 + threadIdx.x;
        float v = tile[threadIdx.x][i];
        __nv_bfloat16 h = __float2bfloat16(v);
        size_t base = (size_t)n * 2 * HID;
        y[base + k]       = h;
        y[base + HID + k] = __float2bfloat16(v - __bfloat162float(h));
    }
}

__global__ void wconv_kernel(const float* __restrict__ W, __nv_bfloat16* __restrict__ y,
                             int K, int N) {
    __shared__ float tile[32][33];
    int n0 = blockIdx.x * 32, k0 = blockIdx.y * 32;
    for (int i = threadIdx.y; i < 32; i += 8)
        tile[i][threadIdx.x] = W[(size_t)(k0 + i) * N + n0 + threadIdx.x];
    __syncthreads();
    for (int i = threadIdx.y; i < 32; i += 8) {
        int n = n0 + i, k = k0 + threadIdx.x;
        float v = tile[threadIdx.x][i];
        __nv_bfloat16 h = __float2bfloat16(v);
        size_t base = (size_t)n * 2 * K;
        y[base + k]     = h;
        y[base + K + k] = __float2bfloat16(v - __bfloat162float(h));
    }
}

__global__ void rmsconv_kernel(const float* __restrict__ x, const float* __restrict__ w,
                               __nv_bfloat16* __restrict__ y) {
    int row = blockIdx.x;
    const float* xr = x + (size_t)row * HID;
    float s = 0.f;
    for (int i = threadIdx.x; i < HID; i += 256) { float v = xr[i]; s += v * v; }
    __shared__ float red[256];
    red[threadIdx.x] = s; __syncthreads();
    for (int st = 128; st > 0; st >>= 1) {
        if (threadIdx.x < st) red[threadIdx.x] += red[threadIdx.x + st];
        __syncthreads();
    }
    float r = rsqrtf(red[0] / (float)HID + 1e-6f);
    size_t base = (size_t)row * 2 * HID;
    for (int i = threadIdx.x; i < HID; i += 256) {
        float v = w[i] * xr[i] * r;
        __nv_bfloat16 h = __float2bfloat16(v);
        y[base + i] = h;
        y[base + HID + i] = __float2bfloat16(v - __bfloat162float(h));
    }
}

// ================= bf16 HMMA GEMM (3-segment hi/lo compensated) =================
#define HG_SMEM 65536

__global__ void __launch_bounds__(256, 2) hgemm_kernel(
    const __nv_bfloat16* __restrict__ A, const __nv_bfloat16* __restrict__ B,
    const float* __restrict__ b1, const float* __restrict__ b2, const float* __restrict__ b3,
    int n1, int n2,
    const float* __restrict__ res,
    float* __restrict__ C, int N, int K)
{
    extern __shared__ char smraw[];
    const uint32_t smu = smem_u32(smraw);
    const int tid = threadIdx.x;
    const int lane = tid & 31, wid = tid >> 5;
    const int wm = wid >> 2, wn = wid & 3;
    const size_t lda = 2 * (size_t)K;
    const int kpseg = K >> 6;
    const int nch = 3 * kpseg;
    const size_t arow0 = (size_t)blockIdx.x * 128;
    const size_t brow0 = (size_t)blockIdx.y * 128;

    float acc[4][4][4];
#pragma unroll
    for (int i = 0; i < 4; i++)
#pragma unroll
        for (int j = 0; j < 4; j++)
#pragma unroll
            for (int t = 0; t < 4; t++) acc[i][j][t] = 0.f;

    auto issue = [&](int ch, int b) {
        int seg = ch / kpseg;
        int kk = (ch - seg * kpseg) << 6;
        const __nv_bfloat16* Ab = A + (seg == 1 ? K : 0) + kk;
        const __nv_bfloat16* Bb = B + (seg == 2 ? K : 0) + kk;
        uint32_t abase = smu + b * 32768;
        uint32_t bbase = abase + 16384;
#pragma unroll
        for (int i = 0; i < 4; i++) {
            int u = i * 256 + tid;
            int r = u >> 3, c = u & 7;
            uint32_t so = sw128((uint32_t)(r * 128 + c * 16));
            cp_async16(abase + so, Ab + (arow0 + r) * lda + c * 8);
            cp_async16(bbase + so, Bb + (brow0 + r) * lda + c * 8);
        }
        cp_commit();
    };

    issue(0, 0);

    for (int ch = 0; ch < nch; ch++) {
        const int b = ch & 1;
        if (ch + 1 < nch) {
            issue(ch + 1, b ^ 1);
            asm volatile("cp.async.wait_group 1;");
        } else {
            asm volatile("cp.async.wait_group 0;");
        }
        __syncthreads();

        const uint32_t abuf = smu + b * 32768;
        const uint32_t bbuf = abuf + 16384;
        const int arow = (wm << 6) + (lane & 15);
        const int brow = (wn << 5) + (lane & 15);
        const int kbl = (lane >> 4) * 16;

#pragma unroll
        for (int ks = 0; ks < 4; ks++) {
            const int kb = ks * 32 + kbl;
            uint32_t a[4][4];
#pragma unroll
            for (int mt = 0; mt < 4; mt++) {
                uint32_t off = (uint32_t)((arow + (mt << 4)) * 128 + kb);
                LDSM_X4(a[mt][0], a[mt][1], a[mt][2], a[mt][3], abuf + sw128(off));
            }
            uint32_t bf[4][2];
#pragma unroll
            for (int nt2 = 0; nt2 < 2; nt2++) {
                uint32_t t0, t1, t2, t3;
                uint32_t off = (uint32_t)((brow + (nt2 << 4)) * 128 + kb);
                LDSM_X4(t0, t1, t2, t3, bbuf + sw128(off));
                bf[nt2 * 2 + 0][0] = t0; bf[nt2 * 2 + 0][1] = t2;
                bf[nt2 * 2 + 1][0] = t1; bf[nt2 * 2 + 1][1] = t3;
            }
#pragma unroll
            for (int mt = 0; mt < 4; mt++)
#pragma unroll
                for (int nt = 0; nt < 4; nt++)
                    MMA16816(acc[mt][nt], a[mt], bf[nt][0], bf[nt][1]);
        }
        __syncthreads();
    }

    const int rbase = (int)arow0 + (wm << 6) + (lane >> 2);
    const int cbase = (int)brow0 + (wn << 5) + ((lane & 3) << 1);
#pragma unroll
    for (int nt = 0; nt < 4; nt++) {
        const int col = cbase + (nt << 3);
        float bv0 = 0.f, bv1 = 0.f;
        if (b1) {
            if (col < n1)       { bv0 = b1[col];      bv1 = b1[col + 1]; }
            else if (col < n2)  { bv0 = b2[col - n1]; bv1 = b2[col - n1 + 1]; }
            else                { bv0 = b3[col - n2]; bv1 = b3[col - n2 + 1]; }
        }
#pragma unroll
        for (int mt = 0; mt < 4; mt++) {
            const int row = rbase + (mt << 4);
            size_t gi = (size_t)row * N + col;
            float v0 = acc[mt][nt][0] + bv0, v1 = acc[mt][nt][1] + bv1;
            if (res) { v0 += res[gi]; v1 += res[gi + 1]; }
            *(float2*)(C + gi) = make_float2(v0, v1);
            size_t gi2 = gi + (size_t)8 * N;
            float v2 = acc[mt][nt][2] + bv0, v3 = acc[mt][nt][3] + bv1;
            if (res) { v2 += res[gi2]; v3 += res[gi2 + 1]; }
            *(float2*)(C + gi2) = make_float2(v2, v3);
        }
    }
}

// ================= small fp32 SGEMM (gate path only) =================
__global__ void __launch_bounds__(256) sgemm_kernel(
    const float* __restrict__ A, const float* __restrict__ B,
    float* __restrict__ C, int M, int N, int K)
{
    __shared__ float As[8][128];
    __shared__ float Bs[8][128];
    const int tid = threadIdx.x;
    const int bx = blockIdx.x * 128;
    const int by = blockIdx.y * 128;
    const int tx = tid & 15;
    const int ty = tid >> 4;
    const int arow = tid >> 1;
    const int acol = (tid & 1) << 2;
    const int brow = tid >> 5;
    const int bcol = (tid & 31) << 2;

    const float* Ap = A + (size_t)(by + arow) * K + acol;
    const float* Bp = B + (size_t)brow * N + bx + bcol;

    float acc[8][8];
#pragma unroll
    for (int i = 0; i < 8; i++)
#pragma unroll
        for (int j = 0; j < 8; j++) acc[i][j] = 0.f;

    for (int k0 = 0; k0 < K; k0 += 8) {
        float4 av = *(const float4*)Ap;
        As[acol + 0][arow] = av.x;
        As[acol + 1][arow] = av.y;
        As[acol + 2][arow] = av.z;
        As[acol + 3][arow] = av.w;
        *(float4*)&Bs[brow][bcol] = *(const float4*)Bp;
        __syncthreads();
#pragma unroll
        for (int kk = 0; kk < 8; kk++) {
            float a[8], bb[8];
            *(float4*)&a[0] = *(const float4*)&As[kk][ty * 8];
            *(float4*)&a[4] = *(const float4*)&As[kk][ty * 8 + 4];
            *(float4*)&bb[0] = *(const float4*)&Bs[kk][tx * 8];
            *(float4*)&bb[4] = *(const float4*)&Bs[kk][tx * 8 + 4];
#pragma unroll
            for (int i = 0; i < 8; i++)
#pragma unroll
                for (int j = 0; j < 8; j++)
                    acc[i][j] += a[i] * bb[j];
        }
        __syncthreads();
        Ap += 8;
        Bp += (size_t)8 * N;
    }

    const int row0 = by + ty * 8;
    const int col0 = bx + tx * 8;
#pragma unroll
    for (int i = 0; i < 8; i++)
#pragma unroll
        for (int j = 0; j < 8; j++)
            C[(size_t)(row0 + i) * N + col0 + j] = acc[i][j];
}

// ================= pooling / gate / rope =================
__global__ void pool_kernel(const float* __restrict__ x, int stride,
                            float* __restrict__ out, int H) {
    int qb = blockIdx.x, h = blockIdx.y, d = threadIdx.x;
    float s = 0.f;
    for (int i = 0; i < BSZ; i++)
        s += x[(size_t)(qb * BSZ + i) * stride + h * DH + d];
    out[((size_t)qb * H + h) * DH + d] = s * (1.f / (float)BSZ);
}

__global__ void gate_kernel(const float* __restrict__ qg, const float* __restrict__ kg,
                            unsigned char* __restrict__ keep) {
    int h = blockIdx.x, qb = blockIdx.y, kb = threadIdx.x;
    const float* qv = qg + ((size_t)qb * HQ + h) * GHD;
    const float* kv = kg + ((size_t)kb * HKV + (h >> 2)) * GHD;
    float s = 0.f;
    for (int d = 0; d < GHD; d++) s += qv[d] * kv[d];
    s *= SCALE_INV_SQRT_128;
    if (kb > qb) s = -1e30f;
    float m = s;
    for (int off = 16; off > 0; off >>= 1)
        m = fmaxf(m, __shfl_xor_sync(0xffffffffu, m, off));
    float e = expf(s - m);
    float sum = e;
    for (int off = 16; off > 0; off >>= 1)
        sum += __shfl_xor_sync(0xffffffffu, sum, off);
    float gate = e / sum;
    bool kp = (kb <= qb) && ((gate >= 0.004f) || (kb == qb));
    keep[((size_t)h * QBN + qb) * QBN + kb] = kp ? 1 : 0;
}

__global__ void rope_kernel(float* __restrict__ x, int stride,
                            const float* __restrict__ cs, const float* __restrict__ sn, int H) {
    int idx = blockIdx.x * blockDim.x + threadIdx.x;
    int d = idx & 63;
    int h = (idx >> 6) % H;
    int s = idx / (64 * H);
    float* p = x + (size_t)s * stride + h * DH;
    float x1 = p[d], x2 = p[d + 64];
    float c1 = cs[(size_t)s * DH + d],      s1 = sn[(size_t)s * DH + d];
    float c2 = cs[(size_t)s * DH + d + 64], s2 = sn[(size_t)s * DH + d + 64];
    p[d]      = x1 * c1 - x2 * s1;
    p[d + 64] = x2 * c2 + x1 * s2;
}

// ================= tf32 tensor-core block-sparse flash attention =================
// Per CTA: one (qb, h). 8 warps: rw = wid&3 (16-row groups), cw = wid>>2.
// S tile 64x64: warp -> rows rw*16..+16, cols cw*32..+32 (4 n8 tiles).
// O tile 64x128: warp -> rows rw*16..+16, cols cw*64..+64 (8 n8 tiles).
#define ATP 132
#define APP 68
#define AQ_OFF   0
#define AK_OFF   (64*ATP)
#define AV_OFF   (2*64*ATP)
#define AP_OFF   (3*64*ATP)
#define ARM_OFF  (AP_OFF + 64*APP)
#define ARL_OFF  (ARM_OFF + 128)
#define AROWM    (ARL_OFF + 128)
#define AROWL    (AROWM + 64)
#define AALF     (AROWL + 64)
#define ATTN_SM_FLOATS (AALF + 64)

__global__ void __launch_bounds__(256, 1) attn_kernel(
    const float* __restrict__ qkv,
    const unsigned char* __restrict__ keep, __nv_bfloat16* __restrict__ oa2)
{
    extern __shared__ float sm[];
    const uint32_t* smu = (const uint32_t*)sm;

    const int qb = QBN - 1 - blockIdx.x;
    const int h = blockIdx.y;
    const int hk = h >> 2;
    const int tid = threadIdx.x;
    const int lane = tid & 31, wid = tid >> 5;
    const int rw = wid & 3, cw = wid >> 2;
    const int g = lane >> 2, qd = lane & 3;
    const int r0 = rw * 16 + g;          // first row this thread touches
    const int r1 = r0 + 8;

    // load Q (scale folded, tf32-rounded)
    for (int i = tid; i < 64 * 32; i += 256) {
        int t = i >> 5, d4 = (i & 31) << 2;
        float4 qv = *(const float4*)&qkv[(size_t)(qb * 64 + t) * NQKV + h * DH + d4];
        float* dst = sm + AQ_OFF + t * ATP + d4;
        dst[0] = tf32r(qv.x * SCALE_INV_SQRT_128);
        dst[1] = tf32r(qv.y * SCALE_INV_SQRT_128);
        dst[2] = tf32r(qv.z * SCALE_INV_SQRT_128);
        dst[3] = tf32r(qv.w * SCALE_INV_SQRT_128);
    }
    if (tid < 64) { sm[AROWM + tid] = -1e30f; sm[AROWL + tid] = 0.f; }

    float oacc[8][4];
#pragma unroll
    for (int i = 0; i < 8; i++)
#pragma unroll
        for (int j = 0; j < 4; j++) oacc[i][j] = 0.f;

    const unsigned char* krow = keep + ((size_t)h * QBN + qb) * QBN;

    for (int kb = 0; kb <= qb; kb++) {
        if (!krow[kb]) continue;
        __syncthreads();    // smem reuse guard (also covers initial Q/rowM writes)

        // load K,V (tf32-rounded)
        for (int i = tid; i < 64 * 32; i += 256) {
            int t = i >> 5, d4 = (i & 31) << 2;
            size_t gi = (size_t)(kb * 64 + t) * NQKV + hk * DH + d4;
            float4 kvv = *(const float4*)&qkv[gi + 2048];
            float* kd = sm + AK_OFF + t * ATP + d4;
            kd[0] = tf32r(kvv.x); kd[1] = tf32r(kvv.y); kd[2] = tf32r(kvv.z); kd[3] = tf32r(kvv.w);
            float4 vvv = *(const float4*)&qkv[gi + 2560];
            float* vd = sm + AV_OFF + t * ATP + d4;
            vd[0] = tf32r(vvv.x); vd[1] = tf32r(vvv.y); vd[2] = tf32r(vvv.z); vd[3] = tf32r(vvv.w);
        }
        __syncthreads();

        // S = Q @ K^T (tf32 mma)
        float sacc[4][4];
#pragma unroll
        for (int i = 0; i < 4; i++)
#pragma unroll
            for (int j = 0; j < 4; j++) sacc[i][j] = 0.f;

#pragma unroll
        for (int ks = 0; ks < 16; ks++) {
            const int k0 = ks * 8;
            uint32_t a[4];
            a[0] = smu[AQ_OFF + r0 * ATP + k0 + qd];
            a[1] = smu[AQ_OFF + r1 * ATP + k0 + qd];
            a[2] = smu[AQ_OFF + r0 * ATP + k0 + qd + 4];
            a[3] = smu[AQ_OFF + r1 * ATP + k0 + qd + 4];
#pragma unroll
            for (int nt = 0; nt < 4; nt++) {
                const int n = cw * 32 + nt * 8 + g;
                uint32_t b0 = smu[AK_OFF + n * ATP + k0 + qd];
                uint32_t b1 = smu[AK_OFF + n * ATP + k0 + qd + 4];
                MMATF32(sacc[nt], a, b0, b1);
            }
        }

        // diag mask
        if (kb == qb) {
#pragma unroll
            for (int nt = 0; nt < 4; nt++) {
                const int c0 = cw * 32 + nt * 8 + qd * 2;
                if (c0 > r0)     sacc[nt][0] = -1e30f;
                if (c0 + 1 > r0) sacc[nt][1] = -1e30f;
                if (c0 > r1)     sacc[nt][2] = -1e30f;
                if (c0 + 1 > r1) sacc[nt][3] = -1e30f;
            }
        }

        // row max (this warp's 32 cols)
        float m0 = -1e30f, m1 = -1e30f;
#pragma unroll
        for (int nt = 0; nt < 4; nt++) {
            m0 = fmaxf(m0, fmaxf(sacc[nt][0], sacc[nt][1]));
            m1 = fmaxf(m1, fmaxf(sacc[nt][2], sacc[nt][3]));
        }
        m0 = fmaxf(m0, __shfl_xor_sync(0xffffffffu, m0, 1));
        m0 = fmaxf(m0, __shfl_xor_sync(0xffffffffu, m0, 2));
        m1 = fmaxf(m1, __shfl_xor_sync(0xffffffffu, m1, 1));
        m1 = fmaxf(m1, __shfl_xor_sync(0xffffffffu, m1, 2));
        if (qd == 0) {
            sm[ARM_OFF + cw * 64 + r0] = m0;
            sm[ARM_OFF + cw * 64 + r1] = m1;
        }
        __syncthreads();

        if (tid < 64) {
            float newm = fmaxf(sm[AROWM + tid],
                               fmaxf(sm[ARM_OFF + tid], sm[ARM_OFF + 64 + tid]));
            sm[AALF + tid] = __expf(sm[AROWM + tid] - newm);
            sm[AROWM + tid] = newm;
        }
        __syncthreads();

        // P = exp(S - m), write to smem; partial row sums; rescale O
        const float nm0 = sm[AROWM + r0];
        const float nm1 = sm[AROWM + r1];
        float l0 = 0.f, l1 = 0.f;
#pragma unroll
        for (int nt = 0; nt < 4; nt++) {
            const int c0 = cw * 32 + nt * 8 + qd * 2;
            float p0 = __expf(sacc[nt][0] - nm0);
            float p1 = __expf(sacc[nt][1] - nm0);
            float p2 = __expf(sacc[nt][2] - nm1);
            float p3 = __expf(sacc[nt][3] - nm1);
            l0 += p0 + p1; l1 += p2 + p3;
            sm[AP_OFF + r0 * APP + c0]     = tf32r(p0);
            sm[AP_OFF + r0 * APP + c0 + 1] = tf32r(p1);
            sm[AP_OFF + r1 * APP + c0]     = tf32r(p2);
            sm[AP_OFF + r1 * APP + c0 + 1] = tf32r(p3);
        }
        l0 += __shfl_xor_sync(0xffffffffu, l0, 1);
        l0 += __shfl_xor_sync(0xffffffffu, l0, 2);
        l1 += __shfl_xor_sync(0xffffffffu, l1, 1);
        l1 += __shfl_xor_sync(0xffffffffu, l1, 2);
        if (qd == 0) {
            sm[ARL_OFF + cw * 64 + r0] = l0;
            sm[ARL_OFF + cw * 64 + r1] = l1;
        }
        const float al0 = sm[AALF + r0];
        const float al1 = sm[AALF + r1];
#pragma unroll
        for (int nt = 0; nt < 8; nt++) {
            oacc[nt][0] *= al0; oacc[nt][1] *= al0;
            oacc[nt][2] *= al1; oacc[nt][3] *= al1;
        }
        __syncthreads();

        if (tid < 64)
            sm[AROWL + tid] = sm[AROWL + tid] * sm[AALF + tid]
                            + sm[ARL_OFF + tid] + sm[ARL_OFF + 64 + tid];

        // O += P @ V (tf32 mma)
#pragma unroll
        for (int ks = 0; ks < 8; ks++) {
            const int k0 = ks * 8;
            uint32_t a[4];
            a[0] = smu[AP_OFF + r0 * APP + k0 + qd];
            a[1] = smu[AP_OFF + r1 * APP + k0 + qd];
            a[2] = smu[AP_OFF + r0 * APP + k0 + qd + 4];
            a[3] = smu[AP_OFF + r1 * APP + k0 + qd + 4];
#pragma unroll
            for (int nt = 0; nt < 8; nt++) {
                const int n = cw * 64 + nt * 8 + g;
                uint32_t b0 = smu[AV_OFF + (k0 + qd) * ATP + n];
                uint32_t b1 = smu[AV_OFF + (k0 + qd + 4) * ATP + n];
                MMATF32(oacc[nt], a, b0, b1);
            }
        }
    }

    __syncthreads();
    const float inv0 = 1.f / sm[AROWL + r0];
    const float inv1 = 1.f / sm[AROWL + r1];
    const size_t grow0 = (size_t)(qb * 64 + r0);
    const size_t grow1 = (size_t)(qb * 64 + r1);
#pragma unroll
    for (int nt = 0; nt < 8; nt++) {
        const int col = h * DH + cw * 64 + nt * 8 + qd * 2;
#pragma unroll
        for (int j = 0; j < 2; j++) {
            float v0 = oacc[nt][j] * inv0;
            __nv_bfloat16 h0 = __float2bfloat16(v0);
            oa2[grow0 * 4096 + col + j] = h0;
            oa2[grow0 * 4096 + 2048 + col + j] = __float2bfloat16(v0 - __bfloat162float(h0));
            float v1 = oacc[nt][j + 2] * inv1;
            __nv_bfloat16 h1 = __float2bfloat16(v1);
            oa2[grow1 * 4096 + col + j] = h1;
            oa2[grow1 * 4096 + 2048 + col + j] = __float2bfloat16(v1 - __bfloat162float(h1));
        }
    }
}

// ================= SiLU(gate)*up fused with bf16 split conversion ============
__global__ void siluconv_kernel(const float* __restrict__ gu, __nv_bfloat16* __restrict__ y) {
    int s = blockIdx.y;
    int j = blockIdx.x * 256 + threadIdx.x;
    size_t row = (size_t)s * NGU;
    float x = gu[row + j];
    float u = gu[row + INTER + j];
    float v = (x / (1.f + __expf(-x))) * u;
    __nv_bfloat16 hi = __float2bfloat16(v);
    y[row + j] = hi;
    y[row + INTER + j] = __float2bfloat16(v - __bfloat162float(hi));
}

// ================= launch =================
extern "C" void kernel_launch(void* const* d_in, const int* in_sizes, int n_in,
                              void* d_out, int out_size) {
    const float* hidden = (const float*)d_in[0];
    const float* cosp   = (const float*)d_in[1];
    const float* sinp   = (const float*)d_in[2];
    const float* ln1    = (const float*)d_in[3];
    const float* ln2    = (const float*)d_in[4];
    const float* Wq     = (const float*)d_in[5];
    const float* bq     = (const float*)d_in[6];
    const float* Wk     = (const float*)d_in[7];
    const float* bk     = (const float*)d_in[8];
    const float* Wv     = (const float*)d_in[9];
    const float* bv     = (const float*)d_in[10];
    const float* Wo     = (const float*)d_in[11];
    const float* gWq    = (const float*)d_in[12];
    const float* gWk    = (const float*)d_in[13];
    const float* Wgate  = (const float*)d_in[14];
    const float* Wup    = (const float*)d_in[15];
    const float* Wdown  = (const float*)d_in[16];
    float* out = (float*)d_out;

    float *qkv, *qp, *kp, *qg, *kg, *h2, *gu;
    unsigned char* keep;
    __nv_bfloat16 *Wqkv2, *Wo2, *Wgu2, *Wd2, *ha2, *oa2, *h3a2, *gt2;
    cudaGetSymbolAddress((void**)&qkv,  g_qkv);
    cudaGetSymbolAddress((void**)&qp,   g_qp);
    cudaGetSymbolAddress((void**)&kp,   g_kp);
    cudaGetSymbolAddress((void**)&qg,   g_qg);
    cudaGetSymbolAddress((void**)&kg,   g_kg);
    cudaGetSymbolAddress((void**)&keep, g_keep);
    cudaGetSymbolAddress((void**)&h2,   g_h2);
    cudaGetSymbolAddress((void**)&gu,   g_gu);
    cudaGetSymbolAddress((void**)&Wqkv2, g_Wqkv2);
    cudaGetSymbolAddress((void**)&Wo2,  g_Wo2);
    cudaGetSymbolAddress((void**)&Wgu2, g_Wgu2);
    cudaGetSymbolAddress((void**)&Wd2,  g_Wd2);
    cudaGetSymbolAddress((void**)&ha2,  g_ha2);
    cudaGetSymbolAddress((void**)&oa2,  g_oa2);
    cudaGetSymbolAddress((void**)&h3a2, g_h3a2);
    cudaGetSymbolAddress((void**)&gt2,  g_gt2);

    cudaFuncSetAttribute(hgemm_kernel, cudaFuncAttributeMaxDynamicSharedMemorySize, HG_SMEM);
    cudaFuncSetAttribute(attn_kernel, cudaFuncAttributeMaxDynamicSharedMemorySize,
                         ATTN_SM_FLOATS * (int)sizeof(float));

    dim3 w8(32, 8);

    wconv3_kernel<<<dim3(NQKV/32, HID/32), w8>>>(Wq, Wk, Wv, Wqkv2);
    rmsconv_kernel<<<SEQ, 256>>>(hidden, ln1, ha2);
    wconv_kernel<<<dim3(HID/32, HID/32), w8>>>(Wo, Wo2, HID, HID);
    hgemm_kernel<<<dim3(SEQ/128, NQKV/128), 256, HG_SMEM>>>(
        ha2, Wqkv2, bq, bk, bv, 2048, 2560, nullptr, qkv, NQKV, HID);

    pool_kernel<<<dim3(QBN, HQ), DH>>>(qkv, NQKV, qp, HQ);
    pool_kernel<<<dim3(QBN, HKV), DH>>>(qkv + 2048, NQKV, kp, HKV);
    sgemm_kernel<<<dim3(GHD/128, (QBN*HQ)/128), 256>>>(qp, gWq, qg, QBN*HQ, GHD, DH);
    sgemm_kernel<<<dim3(GHD/128, (QBN*HKV)/128), 256>>>(kp, gWk, kg, QBN*HKV, GHD, DH);
    gate_kernel<<<dim3(HQ, QBN), 32>>>(qg, kg, keep);

    rope_kernel<<<(SEQ*HQ*64)/256, 256>>>(qkv, NQKV, cosp, sinp, HQ);
    rope_kernel<<<(SEQ*HKV*64)/256, 256>>>(qkv + 2048, NQKV, cosp, sinp, HKV);

    attn_kernel<<<dim3(QBN, HQ), 256, ATTN_SM_FLOATS * (int)sizeof(float)>>>(qkv, keep, oa2);

    hgemm_kernel<<<dim3(SEQ/128, HID/128), 256, HG_SMEM>>>(
        oa2, Wo2, nullptr, nullptr, nullptr, HID, HID, hidden, h2, HID, HQ*DH);

    rmsconv_kernel<<<SEQ, 256>>>(h2, ln2, h3a2);

    wconv_kernel<<<dim3(INTER/32, HID/32), w8>>>(Wgate, Wgu2, HID, INTER);
    wconv_kernel<<<dim3(INTER/32, HID/32), w8>>>(Wup, Wgu2 + (size_t)INTER*4096, HID, INTER);
    hgemm_kernel<<<dim3(SEQ/128, NGU/128), 256, HG_SMEM>>>(
        h3a2, Wgu2, nullptr, nullptr, nullptr, NGU, NGU, nullptr, gu, NGU, HID);

    wconv_kernel<<<dim3(HID/32, INTER/32), w8>>>(Wdown, Wd2, INTER, HID);
    siluconv_kernel<<<dim3(INTER/256, SEQ), 256>>>(gu, gt2);

    hgemm_kernel<<<dim3(SEQ/128, HID/128), 256, HG_SMEM>>>(
        gt2, Wd2, nullptr, nullptr, nullptr, HID, HID, h2, out, HID, INTER);
}

// round 7
// speedup vs baseline: 3.3629x; 1.0848x over previous
#include <cuda_runtime.h>
#include <cuda_bf16.h>
#include <math.h>
#include <stdint.h>

#define SEQ   2048
#define HID   2048
#define HQ    16
#define HKV   4
#define DH    128
#define QBN   32
#define BSZ   64
#define GHD   128
#define INTER 5632
#define NQKV  3072
#define NGU   11264

#define SCALE_INV_SQRT_128 0.08838834764831845f

// ================= helpers =================
__device__ __forceinline__ uint32_t smem_u32(const void* p) {
    uint32_t a;
    asm("{ .reg .u64 t; cvta.to.shared.u64 t, %1; cvt.u32.u64 %0, t; }" : "=r"(a) : "l"(p));
    return a;
}
__device__ __forceinline__ void cp_async16(uint32_t saddr, const void* gptr) {
    asm volatile("cp.async.cg.shared.global [%0], [%1], 16;" :: "r"(saddr), "l"(gptr));
}
__device__ __forceinline__ void cp_commit() { asm volatile("cp.async.commit_group;"); }

#define LDSM_X4(r0, r1, r2, r3, addr) \
    asm volatile("ldmatrix.sync.aligned.m8n8.x4.shared.b16 {%0,%1,%2,%3}, [%4];" \
        : "=r"(r0), "=r"(r1), "=r"(r2), "=r"(r3) : "r"(addr))

#define MMA16816(c, a, b0r, b1r) \
    asm volatile("mma.sync.aligned.m16n8k16.row.col.f32.bf16.bf16.f32 " \
        "{%0,%1,%2,%3}, {%4,%5,%6,%7}, {%8,%9}, {%0,%1,%2,%3};" \
        : "+f"((c)[0]), "+f"((c)[1]), "+f"((c)[2]), "+f"((c)[3]) \
        : "r"((a)[0]), "r"((a)[1]), "r"((a)[2]), "r"((a)[3]), "r"(b0r), "r"(b1r))

#define MMATF32(c, a, b0r, b1r) \
    asm volatile("mma.sync.aligned.m16n8k8.row.col.f32.tf32.tf32.f32 " \
        "{%0,%1,%2,%3}, {%4,%5,%6,%7}, {%8,%9}, {%0,%1,%2,%3};" \
        : "+f"((c)[0]), "+f"((c)[1]), "+f"((c)[2]), "+f"((c)[3]) \
        : "r"((a)[0]), "r"((a)[1]), "r"((a)[2]), "r"((a)[3]), "r"(b0r), "r"(b1r))

static __device__ __forceinline__ uint32_t sw128(uint32_t o) { return o ^ ((o >> 3) & 0x70); }

__device__ __forceinline__ float tf32r(float v) {
    float r;
    asm("cvt.rna.tf32.f32 %0, %1;" : "=f"(r) : "f"(v));
    return r;
}

// ================= device scratch =================
__device__ float g_qkv [SEQ*NQKV];
__device__ float g_qp  [QBN*HQ*DH];
__device__ float g_kp  [QBN*HKV*DH];
__device__ float g_qg  [QBN*HQ*GHD];
__device__ float g_kg  [QBN*HKV*GHD];
__device__ unsigned char g_keep[HQ*QBN*QBN];
__device__ float g_h2  [SEQ*HID];
__device__ float g_gu  [SEQ*NGU];

__device__ __nv_bfloat16 g_Wqkv2[NQKV*4096];
__device__ __nv_bfloat16 g_Wo2  [2048*4096];
__device__ __nv_bfloat16 g_Wgu2 [NGU*4096];
__device__ __nv_bfloat16 g_Wd2  [2048*11264];
__device__ __nv_bfloat16 g_ha2  [2048*4096];
__device__ __nv_bfloat16 g_oa2  [2048*4096];
__device__ __nv_bfloat16 g_h3a2 [2048*4096];
__device__ __nv_bfloat16 g_gt2  [2048*11264];

// ===== side-stream resources (created pre-main in static init) =====
struct AuxRes {
    cudaStream_t s2;
    cudaEvent_t root, evQKV, evWo, evGU, evWd;
    AuxRes() {
        cudaStreamCreateWithFlags(&s2, cudaStreamNonBlocking);
        cudaEventCreateWithFlags(&root,  cudaEventDisableTiming);
        cudaEventCreateWithFlags(&evQKV, cudaEventDisableTiming);
        cudaEventCreateWithFlags(&evWo,  cudaEventDisableTiming);
        cudaEventCreateWithFlags(&evGU,  cudaEventDisableTiming);
        cudaEventCreateWithFlags(&evWd,  cudaEventDisableTiming);
    }
};
static AuxRes g_aux;

// ===== fused QKV weight conversion =====
__global__ void wconv3_kernel(const float* __restrict__ Wq, const float* __restrict__ Wk,
                              const float* __restrict__ Wv, __nv_bfloat16* __restrict__ y) {
    __shared__ float tile[32][33];
    int n0 = blockIdx.x * 32, k0 = blockIdx.y * 32;
    const float* W; int sN, c0;
    if (n0 < 2048)      { W = Wq; sN = 2048; c0 = n0; }
    else if (n0 < 2560) { W = Wk; sN = 512;  c0 = n0 - 2048; }
    else                { W = Wv; sN = 512;  c0 = n0 - 2560; }
    for (int i = threadIdx.y; i < 32; i += 8)
        tile[i][threadIdx.x] = W[(size_t)(k0 + i) * sN + c0 + threadIdx.x];
    __syncthreads();
    for (int i = threadIdx.y; i < 32; i += 8) {
        int n = n0 + i, k = k0 + threadIdx.x;
        float v = tile[threadIdx.x][i];
        __nv_bfloat16 h = __float2bfloat16(v);
        size_t base = (size_t)n * 2 * HID;
        y[base + k]       = h;
        y[base + HID + k] = __float2bfloat16(v - __bfloat162float(h));
    }
}

__global__ void wconv_kernel(const float* __restrict__ W, __nv_bfloat16* __restrict__ y,
                             int K, int N) {
    __shared__ float tile[32][33];
    int n0 = blockIdx.x * 32, k0 = blockIdx.y * 32;
    for (int i = threadIdx.y; i < 32; i += 8)
        tile[i][threadIdx.x] = W[(size_t)(k0 + i) * N + n0 + threadIdx.x];
    __syncthreads();
    for (int i = threadIdx.y; i < 32; i += 8) {
        int n = n0 + i, k = k0 + threadIdx.x;
        float v = tile[threadIdx.x][i];
        __nv_bfloat16 h = __float2bfloat16(v);
        size_t base = (size_t)n * 2 * K;
        y[base + k]     = h;
        y[base + K + k] = __float2bfloat16(v - __bfloat162float(h));
    }
}

__global__ void rmsconv_kernel(const float* __restrict__ x, const float* __restrict__ w,
                               __nv_bfloat16* __restrict__ y) {
    int row = blockIdx.x;
    const float* xr = x + (size_t)row * HID;
    float s = 0.f;
    for (int i = threadIdx.x; i < HID; i += 256) { float v = xr[i]; s += v * v; }
    __shared__ float red[256];
    red[threadIdx.x] = s; __syncthreads();
    for (int st = 128; st > 0; st >>= 1) {
        if (threadIdx.x < st) red[threadIdx.x] += red[threadIdx.x + st];
        __syncthreads();
    }
    float r = rsqrtf(red[0] / (float)HID + 1e-6f);
    size_t base = (size_t)row * 2 * HID;
    for (int i = threadIdx.x; i < HID; i += 256) {
        float v = w[i] * xr[i] * r;
        __nv_bfloat16 h = __float2bfloat16(v);
        y[base + i] = h;
        y[base + HID + i] = __float2bfloat16(v - __bfloat162float(h));
    }
}

// ================= bf16 HMMA GEMM (3-segment hi/lo compensated) =================
#define HG_SMEM 65536

__global__ void __launch_bounds__(256, 2) hgemm_kernel(
    const __nv_bfloat16* __restrict__ A, const __nv_bfloat16* __restrict__ B,
    const float* __restrict__ b1, const float* __restrict__ b2, const float* __restrict__ b3,
    int n1, int n2,
    const float* __restrict__ res,
    float* __restrict__ C, int N, int K)
{
    extern __shared__ char smraw[];
    const uint32_t smu = smem_u32(smraw);
    const int tid = threadIdx.x;
    const int lane = tid & 31, wid = tid >> 5;
    const int wm = wid >> 2, wn = wid & 3;
    const size_t lda = 2 * (size_t)K;
    const int kpseg = K >> 6;
    const int nch = 3 * kpseg;
    const size_t arow0 = (size_t)blockIdx.x * 128;
    const size_t brow0 = (size_t)blockIdx.y * 128;

    // decomposed swizzle for ldmatrix addressing:
    // sw128(row*128+cb) = row*128 + (cb ^ ((lane&7)<<4)) for all our rows
    const int kbl = (lane >> 4) * 16;
    const uint32_t xm = (uint32_t)((lane & 7) << 4);
    uint32_t kbx[4];
#pragma unroll
    for (int ks = 0; ks < 4; ks++) kbx[ks] = ((uint32_t)(ks * 32 + kbl)) ^ xm;
    const uint32_t arow = (uint32_t)((wm << 6) + (lane & 15));
    const uint32_t brow = (uint32_t)((wn << 5) + (lane & 15));
    uint32_t rowA[4], rowB[2];
#pragma unroll
    for (int mt = 0; mt < 4; mt++) rowA[mt] = (arow + (mt << 4)) * 128u;
#pragma unroll
    for (int nt2 = 0; nt2 < 2; nt2++) rowB[nt2] = (brow + (nt2 << 4)) * 128u;

    float acc[4][4][4];
#pragma unroll
    for (int i = 0; i < 4; i++)
#pragma unroll
        for (int j = 0; j < 4; j++)
#pragma unroll
            for (int t = 0; t < 4; t++) acc[i][j][t] = 0.f;

    auto issue = [&](int ch, int b) {
        int seg = ch / kpseg;
        int kk = (ch - seg * kpseg) << 6;
        const __nv_bfloat16* Ab = A + (seg == 1 ? K : 0) + kk;
        const __nv_bfloat16* Bb = B + (seg == 2 ? K : 0) + kk;
        uint32_t abase = smu + b * 32768;
        uint32_t bbase = abase + 16384;
#pragma unroll
        for (int i = 0; i < 4; i++) {
            int u = i * 256 + tid;
            int r = u >> 3, c = u & 7;
            uint32_t so = sw128((uint32_t)(r * 128 + c * 16));
            cp_async16(abase + so, Ab + (arow0 + r) * lda + c * 8);
            cp_async16(bbase + so, Bb + (brow0 + r) * lda + c * 8);
        }
        cp_commit();
    };

    issue(0, 0);

    for (int ch = 0; ch < nch; ch++) {
        const int b = ch & 1;
        if (ch + 1 < nch) {
            issue(ch + 1, b ^ 1);
            asm volatile("cp.async.wait_group 1;");
        } else {
            asm volatile("cp.async.wait_group 0;");
        }
        __syncthreads();

        const uint32_t abuf = smu + b * 32768;
        const uint32_t bbuf = abuf + 16384;

#pragma unroll
        for (int ks = 0; ks < 4; ks++) {
            uint32_t a[4][4];
#pragma unroll
            for (int mt = 0; mt < 4; mt++)
                LDSM_X4(a[mt][0], a[mt][1], a[mt][2], a[mt][3],
                        abuf + rowA[mt] + kbx[ks]);
            uint32_t bf[4][2];
#pragma unroll
            for (int nt2 = 0; nt2 < 2; nt2++) {
                uint32_t t0, t1, t2, t3;
                LDSM_X4(t0, t1, t2, t3, bbuf + rowB[nt2] + kbx[ks]);
                bf[nt2 * 2 + 0][0] = t0; bf[nt2 * 2 + 0][1] = t2;
                bf[nt2 * 2 + 1][0] = t1; bf[nt2 * 2 + 1][1] = t3;
            }
#pragma unroll
            for (int mt = 0; mt < 4; mt++)
#pragma unroll
                for (int nt = 0; nt < 4; nt++)
                    MMA16816(acc[mt][nt], a[mt], bf[nt][0], bf[nt][1]);
        }
        __syncthreads();
    }

    const int rbase = (int)arow0 + (wm << 6) + (lane >> 2);
    const int cbase = (int)brow0 + (wn << 5) + ((lane & 3) << 1);
#pragma unroll
    for (int nt = 0; nt < 4; nt++) {
        const int col = cbase + (nt << 3);
        float bv0 = 0.f, bv1 = 0.f;
        if (b1) {
            if (col < n1)       { bv0 = b1[col];      bv1 = b1[col + 1]; }
            else if (col < n2)  { bv0 = b2[col - n1]; bv1 = b2[col - n1 + 1]; }
            else                { bv0 = b3[col - n2]; bv1 = b3[col - n2 + 1]; }
        }
#pragma unroll
        for (int mt = 0; mt < 4; mt++) {
            const int row = rbase + (mt << 4);
            size_t gi = (size_t)row * N + col;
            float v0 = acc[mt][nt][0] + bv0, v1 = acc[mt][nt][1] + bv1;
            if (res) { v0 += res[gi]; v1 += res[gi + 1]; }
            *(float2*)(C + gi) = make_float2(v0, v1);
            size_t gi2 = gi + (size_t)8 * N;
            float v2 = acc[mt][nt][2] + bv0, v3 = acc[mt][nt][3] + bv1;
            if (res) { v2 += res[gi2]; v3 += res[gi2 + 1]; }
            *(float2*)(C + gi2) = make_float2(v2, v3);
        }
    }
}

// ================= small fp32 SGEMM (gate path only) =================
__global__ void __launch_bounds__(256) sgemm_kernel(
    const float* __restrict__ A, const float* __restrict__ B,
    float* __restrict__ C, int M, int N, int K)
{
    __shared__ float As[8][128];
    __shared__ float Bs[8][128];
    const int tid = threadIdx.x;
    const int bx = blockIdx.x * 128;
    const int by = blockIdx.y * 128;
    const int tx = tid & 15;
    const int ty = tid >> 4;
    const int arow = tid >> 1;
    const int acol = (tid & 1) << 2;
    const int brow = tid >> 5;
    const int bcol = (tid & 31) << 2;

    const float* Ap = A + (size_t)(by + arow) * K + acol;
    const float* Bp = B + (size_t)brow * N + bx + bcol;

    float acc[8][8];
#pragma unroll
    for (int i = 0; i < 8; i++)
#pragma unroll
        for (int j = 0; j < 8; j++) acc[i][j] = 0.f;

    for (int k0 = 0; k0 < K; k0 += 8) {
        float4 av = *(const float4*)Ap;
        As[acol + 0][arow] = av.x;
        As[acol + 1][arow] = av.y;
        As[acol + 2][arow] = av.z;
        As[acol + 3][arow] = av.w;
        *(float4*)&Bs[brow][bcol] = *(const float4*)Bp;
        __syncthreads();
#pragma unroll
        for (int kk = 0; kk < 8; kk++) {
            float a[8], bb[8];
            *(float4*)&a[0] = *(const float4*)&As[kk][ty * 8];
            *(float4*)&a[4] = *(const float4*)&As[kk][ty * 8 + 4];
            *(float4*)&bb[0] = *(const float4*)&Bs[kk][tx * 8];
            *(float4*)&bb[4] = *(const float4*)&Bs[kk][tx * 8 + 4];
#pragma unroll
            for (int i = 0; i < 8; i++)
#pragma unroll
                for (int j = 0; j < 8; j++)
                    acc[i][j] += a[i] * bb[j];
        }
        __syncthreads();
        Ap += 8;
        Bp += (size_t)8 * N;
    }

    const int row0 = by + ty * 8;
    const int col0 = bx + tx * 8;
#pragma unroll
    for (int i = 0; i < 8; i++)
#pragma unroll
        for (int j = 0; j < 8; j++)
            C[(size_t)(row0 + i) * N + col0 + j] = acc[i][j];
}

// ================= pooling / gate / rope =================
__global__ void pool_kernel(const float* __restrict__ x, int stride,
                            float* __restrict__ out, int H) {
    int qb = blockIdx.x, h = blockIdx.y, d = threadIdx.x;
    float s = 0.f;
    for (int i = 0; i < BSZ; i++)
        s += x[(size_t)(qb * BSZ + i) * stride + h * DH + d];
    out[((size_t)qb * H + h) * DH + d] = s * (1.f / (float)BSZ);
}

__global__ void gate_kernel(const float* __restrict__ qg, const float* __restrict__ kg,
                            unsigned char* __restrict__ keep) {
    int h = blockIdx.x, qb = blockIdx.y, kb = threadIdx.x;
    const float* qv = qg + ((size_t)qb * HQ + h) * GHD;
    const float* kv = kg + ((size_t)kb * HKV + (h >> 2)) * GHD;
    float s = 0.f;
    for (int d = 0; d < GHD; d++) s += qv[d] * kv[d];
    s *= SCALE_INV_SQRT_128;
    if (kb > qb) s = -1e30f;
    float m = s;
    for (int off = 16; off > 0; off >>= 1)
        m = fmaxf(m, __shfl_xor_sync(0xffffffffu, m, off));
    float e = expf(s - m);
    float sum = e;
    for (int off = 16; off > 0; off >>= 1)
        sum += __shfl_xor_sync(0xffffffffu, sum, off);
    float gate = e / sum;
    bool kp = (kb <= qb) && ((gate >= 0.004f) || (kb == qb));
    keep[((size_t)h * QBN + qb) * QBN + kb] = kp ? 1 : 0;
}

__global__ void rope_kernel(float* __restrict__ x, int stride,
                            const float* __restrict__ cs, const float* __restrict__ sn, int H) {
    int idx = blockIdx.x * blockDim.x + threadIdx.x;
    int d = idx & 63;
    int h = (idx >> 6) % H;
    int s = idx / (64 * H);
    float* p = x + (size_t)s * stride + h * DH;
    float x1 = p[d], x2 = p[d + 64];
    float c1 = cs[(size_t)s * DH + d],      s1 = sn[(size_t)s * DH + d];
    float c2 = cs[(size_t)s * DH + d + 64], s2 = sn[(size_t)s * DH + d + 64];
    p[d]      = x1 * c1 - x2 * s1;
    p[d + 64] = x2 * c2 + x1 * s2;
}

// ================= tf32 tensor-core block-sparse flash attention =================
#define ATP 132
#define APP 68
#define AQ_OFF   0
#define AK_OFF   (64*ATP)
#define AV_OFF   (2*64*ATP)
#define AP_OFF   (3*64*ATP)
#define ARM_OFF  (AP_OFF + 64*APP)
#define ARL_OFF  (ARM_OFF + 128)
#define AROWM    (ARL_OFF + 128)
#define AROWL    (AROWM + 64)
#define AALF     (AROWL + 64)
#define ATTN_SM_FLOATS (AALF + 64)

__global__ void __launch_bounds__(256, 1) attn_kernel(
    const float* __restrict__ qkv,
    const unsigned char* __restrict__ keep, __nv_bfloat16* __restrict__ oa2)
{
    extern __shared__ float sm[];
    const uint32_t* smu = (const uint32_t*)sm;

    const int qb = QBN - 1 - blockIdx.x;
    const int h = blockIdx.y;
    const int hk = h >> 2;
    const int tid = threadIdx.x;
    const int lane = tid & 31, wid = tid >> 5;
    const int rw = wid & 3, cw = wid >> 2;
    const int g = lane >> 2, qd = lane & 3;
    const int r0 = rw * 16 + g;
    const int r1 = r0 + 8;

    for (int i = tid; i < 64 * 32; i += 256) {
        int t = i >> 5, d4 = (i & 31) << 2;
        float4 qv = *(const float4*)&qkv[(size_t)(qb * 64 + t) * NQKV + h * DH + d4];
        float* dst = sm + AQ_OFF + t * ATP + d4;
        dst[0] = tf32r(qv.x * SCALE_INV_SQRT_128);
        dst[1] = tf32r(qv.y * SCALE_INV_SQRT_128);
        dst[2] = tf32r(qv.z * SCALE_INV_SQRT_128);
        dst[3] = tf32r(qv.w * SCALE_INV_SQRT_128);
    }
    if (tid < 64) { sm[AROWM + tid] = -1e30f; sm[AROWL + tid] = 0.f; }

    float oacc[8][4];
#pragma unroll
    for (int i = 0; i < 8; i++)
#pragma unroll
        for (int j = 0; j < 4; j++) oacc[i][j] = 0.f;

    const unsigned char* krow = keep + ((size_t)h * QBN + qb) * QBN;

    for (int kb = 0; kb <= qb; kb++) {
        if (!krow[kb]) continue;
        __syncthreads();

        for (int i = tid; i < 64 * 32; i += 256) {
            int t = i >> 5, d4 = (i & 31) << 2;
            size_t gi = (size_t)(kb * 64 + t) * NQKV + hk * DH + d4;
            float4 kvv = *(const float4*)&qkv[gi + 2048];
            float* kd = sm + AK_OFF + t * ATP + d4;
            kd[0] = tf32r(kvv.x); kd[1] = tf32r(kvv.y); kd[2] = tf32r(kvv.z); kd[3] = tf32r(kvv.w);
            float4 vvv = *(const float4*)&qkv[gi + 2560];
            float* vd = sm + AV_OFF + t * ATP + d4;
            vd[0] = tf32r(vvv.x); vd[1] = tf32r(vvv.y); vd[2] = tf32r(vvv.z); vd[3] = tf32r(vvv.w);
        }
        __syncthreads();

        float sacc[4][4];
#pragma unroll
        for (int i = 0; i < 4; i++)
#pragma unroll
            for (int j = 0; j < 4; j++) sacc[i][j] = 0.f;

#pragma unroll
        for (int ks = 0; ks < 16; ks++) {
            const int k0 = ks * 8;
            uint32_t a[4];
            a[0] = smu[AQ_OFF + r0 * ATP + k0 + qd];
            a[1] = smu[AQ_OFF + r1 * ATP + k0 + qd];
            a[2] = smu[AQ_OFF + r0 * ATP + k0 + qd + 4];
            a[3] = smu[AQ_OFF + r1 * ATP + k0 + qd + 4];
#pragma unroll
            for (int nt = 0; nt < 4; nt++) {
                const int n = cw * 32 + nt * 8 + g;
                uint32_t b0 = smu[AK_OFF + n * ATP + k0 + qd];
                uint32_t b1 = smu[AK_OFF + n * ATP + k0 + qd + 4];
                MMATF32(sacc[nt], a, b0, b1);
            }
        }

        if (kb == qb) {
#pragma unroll
            for (int nt = 0; nt < 4; nt++) {
                const int c0 = cw * 32 + nt * 8 + qd * 2;
                if (c0 > r0)     sacc[nt][0] = -1e30f;
                if (c0 + 1 > r0) sacc[nt][1] = -1e30f;
                if (c0 > r1)     sacc[nt][2] = -1e30f;
                if (c0 + 1 > r1) sacc[nt][3] = -1e30f;
            }
        }

        float m0 = -1e30f, m1 = -1e30f;
#pragma unroll
        for (int nt = 0; nt < 4; nt++) {
            m0 = fmaxf(m0, fmaxf(sacc[nt][0], sacc[nt][1]));
            m1 = fmaxf(m1, fmaxf(sacc[nt][2], sacc[nt][3]));
        }
        m0 = fmaxf(m0, __shfl_xor_sync(0xffffffffu, m0, 1));
        m0 = fmaxf(m0, __shfl_xor_sync(0xffffffffu, m0, 2));
        m1 = fmaxf(m1, __shfl_xor_sync(0xffffffffu, m1, 1));
        m1 = fmaxf(m1, __shfl_xor_sync(0xffffffffu, m1, 2));
        if (qd == 0) {
            sm[ARM_OFF + cw * 64 + r0] = m0;
            sm[ARM_OFF + cw * 64 + r1] = m1;
        }
        __syncthreads();

        if (tid < 64) {
            float newm = fmaxf(sm[AROWM + tid],
                               fmaxf(sm[ARM_OFF + tid], sm[ARM_OFF + 64 + tid]));
            sm[AALF + tid] = __expf(sm[AROWM + tid] - newm);
            sm[AROWM + tid] = newm;
        }
        __syncthreads();

        const float nm0 = sm[AROWM + r0];
        const float nm1 = sm[AROWM + r1];
        float l0 = 0.f, l1 = 0.f;
#pragma unroll
        for (int nt = 0; nt < 4; nt++) {
            const int c0 = cw * 32 + nt * 8 + qd * 2;
            float p0 = __expf(sacc[nt][0] - nm0);
            float p1 = __expf(sacc[nt][1] - nm0);
            float p2 = __expf(sacc[nt][2] - nm1);
            float p3 = __expf(sacc[nt][3] - nm1);
            l0 += p0 + p1; l1 += p2 + p3;
            sm[AP_OFF + r0 * APP + c0]     = tf32r(p0);
            sm[AP_OFF + r0 * APP + c0 + 1] = tf32r(p1);
            sm[AP_OFF + r1 * APP + c0]     = tf32r(p2);
            sm[AP_OFF + r1 * APP + c0 + 1] = tf32r(p3);
        }
        l0 += __shfl_xor_sync(0xffffffffu, l0, 1);
        l0 += __shfl_xor_sync(0xffffffffu, l0, 2);
        l1 += __shfl_xor_sync(0xffffffffu, l1, 1);
        l1 += __shfl_xor_sync(0xffffffffu, l1, 2);
        if (qd == 0) {
            sm[ARL_OFF + cw * 64 + r0] = l0;
            sm[ARL_OFF + cw * 64 + r1] = l1;
        }
        const float al0 = sm[AALF + r0];
        const float al1 = sm[AALF + r1];
#pragma unroll
        for (int nt = 0; nt < 8; nt++) {
            oacc[nt][0] *= al0; oacc[nt][1] *= al0;
            oacc[nt][2] *= al1; oacc[nt][3] *= al1;
        }
        __syncthreads();

        if (tid < 64)
            sm[AROWL + tid] = sm[AROWL + tid] * sm[AALF + tid]
                            + sm[ARL_OFF + tid] + sm[ARL_OFF + 64 + tid];

#pragma unroll
        for (int ks = 0; ks < 8; ks++) {
            const int k0 = ks * 8;
            uint32_t a[4];
            a[0] = smu[AP_OFF + r0 * APP + k0 + qd];
            a[1] = smu[AP_OFF + r1 * APP + k0 + qd];
            a[2] = smu[AP_OFF + r0 * APP + k0 + qd + 4];
            a[3] = smu[AP_OFF + r1 * APP + k0 + qd + 4];
#pragma unroll
            for (int nt = 0; nt < 8; nt++) {
                const int n = cw * 64 + nt * 8 + g;
                uint32_t b0 = smu[AV_OFF + (k0 + qd) * ATP + n];
                uint32_t b1 = smu[AV_OFF + (k0 + qd + 4) * ATP + n];
                MMATF32(oacc[nt], a, b0, b1);
            }
        }
    }

    __syncthreads();
    const float inv0 = 1.f / sm[AROWL + r0];
    const float inv1 = 1.f / sm[AROWL + r1];
    const size_t grow0 = (size_t)(qb * 64 + r0);
    const size_t grow1 = (size_t)(qb * 64 + r1);
#pragma unroll
    for (int nt = 0; nt < 8; nt++) {
        const int col = h * DH + cw * 64 + nt * 8 + qd * 2;
#pragma unroll
        for (int j = 0; j < 2; j++) {
            float v0 = oacc[nt][j] * inv0;
            __nv_bfloat16 h0 = __float2bfloat16(v0);
            oa2[grow0 * 4096 + col + j] = h0;
            oa2[grow0 * 4096 + 2048 + col + j] = __float2bfloat16(v0 - __bfloat162float(h0));
            float v1 = oacc[nt][j + 2] * inv1;
            __nv_bfloat16 h1 = __float2bfloat16(v1);
            oa2[grow1 * 4096 + col + j] = h1;
            oa2[grow1 * 4096 + 2048 + col + j] = __float2bfloat16(v1 - __bfloat162float(h1));
        }
    }
}

// ================= SiLU(gate)*up fused with bf16 split conversion ============
__global__ void siluconv_kernel(const float* __restrict__ gu, __nv_bfloat16* __restrict__ y) {
    int s = blockIdx.y;
    int j = blockIdx.x * 256 + threadIdx.x;
    size_t row = (size_t)s * NGU;
    float x = gu[row + j];
    float u = gu[row + INTER + j];
    float v = (x / (1.f + __expf(-x))) * u;
    __nv_bfloat16 hi = __float2bfloat16(v);
    y[row + j] = hi;
    y[row + INTER + j] = __float2bfloat16(v - __bfloat162float(hi));
}

// ================= launch =================
extern "C" void kernel_launch(void* const* d_in, const int* in_sizes, int n_in,
                              void* d_out, int out_size) {
    const float* hidden = (const float*)d_in[0];
    const float* cosp   = (const float*)d_in[1];
    const float* sinp   = (const float*)d_in[2];
    const float* ln1    = (const float*)d_in[3];
    const float* ln2    = (const float*)d_in[4];
    const float* Wq     = (const float*)d_in[5];
    const float* bq     = (const float*)d_in[6];
    const float* Wk     = (const float*)d_in[7];
    const float* bk     = (const float*)d_in[8];
    const float* Wv     = (const float*)d_in[9];
    const float* bv     = (const float*)d_in[10];
    const float* Wo     = (const float*)d_in[11];
    const float* gWq    = (const float*)d_in[12];
    const float* gWk    = (const float*)d_in[13];
    const float* Wgate  = (const float*)d_in[14];
    const float* Wup    = (const float*)d_in[15];
    const float* Wdown  = (const float*)d_in[16];
    float* out = (float*)d_out;

    float *qkv, *qp, *kp, *qg, *kg, *h2, *gu;
    unsigned char* keep;
    __nv_bfloat16 *Wqkv2, *Wo2, *Wgu2, *Wd2, *ha2, *oa2, *h3a2, *gt2;
    cudaGetSymbolAddress((void**)&qkv,  g_qkv);
    cudaGetSymbolAddress((void**)&qp,   g_qp);
    cudaGetSymbolAddress((void**)&kp,   g_kp);
    cudaGetSymbolAddress((void**)&qg,   g_qg);
    cudaGetSymbolAddress((void**)&kg,   g_kg);
    cudaGetSymbolAddress((void**)&keep, g_keep);
    cudaGetSymbolAddress((void**)&h2,   g_h2);
    cudaGetSymbolAddress((void**)&gu,   g_gu);
    cudaGetSymbolAddress((void**)&Wqkv2, g_Wqkv2);
    cudaGetSymbolAddress((void**)&Wo2,  g_Wo2);
    cudaGetSymbolAddress((void**)&Wgu2, g_Wgu2);
    cudaGetSymbolAddress((void**)&Wd2,  g_Wd2);
    cudaGetSymbolAddress((void**)&ha2,  g_ha2);
    cudaGetSymbolAddress((void**)&oa2,  g_oa2);
    cudaGetSymbolAddress((void**)&h3a2, g_h3a2);
    cudaGetSymbolAddress((void**)&gt2,  g_gt2);

    cudaFuncSetAttribute(hgemm_kernel, cudaFuncAttributeMaxDynamicSharedMemorySize, HG_SMEM);
    cudaFuncSetAttribute(attn_kernel, cudaFuncAttributeMaxDynamicSharedMemorySize,
                         ATTN_SM_FLOATS * (int)sizeof(float));

    dim3 w8(32, 8);
    cudaStream_t s2 = g_aux.s2;

    // ---- fork side stream: all weight conversions off the critical path ----
    cudaEventRecord(g_aux.root, 0);
    cudaStreamWaitEvent(s2, g_aux.root, 0);
    wconv3_kernel<<<dim3(NQKV/32, HID/32), w8, 0, s2>>>(Wq, Wk, Wv, Wqkv2);
    cudaEventRecord(g_aux.evQKV, s2);
    wconv_kernel<<<dim3(HID/32, HID/32), w8, 0, s2>>>(Wo, Wo2, HID, HID);
    cudaEventRecord(g_aux.evWo, s2);
    wconv_kernel<<<dim3(INTER/32, HID/32), w8, 0, s2>>>(Wgate, Wgu2, HID, INTER);
    wconv_kernel<<<dim3(INTER/32, HID/32), w8, 0, s2>>>(Wup, Wgu2 + (size_t)INTER*4096, HID, INTER);
    cudaEventRecord(g_aux.evGU, s2);
    wconv_kernel<<<dim3(HID/32, INTER/32), w8, 0, s2>>>(Wdown, Wd2, INTER, HID);
    cudaEventRecord(g_aux.evWd, s2);

    // ---- main chain ----
    rmsconv_kernel<<<SEQ, 256>>>(hidden, ln1, ha2);
    cudaStreamWaitEvent(0, g_aux.evQKV, 0);
    hgemm_kernel<<<dim3(SEQ/128, NQKV/128), 256, HG_SMEM>>>(
        ha2, Wqkv2, bq, bk, bv, 2048, 2560, nullptr, qkv, NQKV, HID);

    pool_kernel<<<dim3(QBN, HQ), DH>>>(qkv, NQKV, qp, HQ);
    pool_kernel<<<dim3(QBN, HKV), DH>>>(qkv + 2048, NQKV, kp, HKV);
    sgemm_kernel<<<dim3(GHD/128, (QBN*HQ)/128), 256>>>(qp, gWq, qg, QBN*HQ, GHD, DH);
    sgemm_kernel<<<dim3(GHD/128, (QBN*HKV)/128), 256>>>(kp, gWk, kg, QBN*HKV, GHD, DH);
    gate_kernel<<<dim3(HQ, QBN), 32>>>(qg, kg, keep);

    rope_kernel<<<(SEQ*HQ*64)/256, 256>>>(qkv, NQKV, cosp, sinp, HQ);
    rope_kernel<<<(SEQ*HKV*64)/256, 256>>>(qkv + 2048, NQKV, cosp, sinp, HKV);

    attn_kernel<<<dim3(QBN, HQ), 256, ATTN_SM_FLOATS * (int)sizeof(float)>>>(qkv, keep, oa2);

    cudaStreamWaitEvent(0, g_aux.evWo, 0);
    hgemm_kernel<<<dim3(SEQ/128, HID/128), 256, HG_SMEM>>>(
        oa2, Wo2, nullptr, nullptr, nullptr, HID, HID, hidden, h2, HID, HQ*DH);

    rmsconv_kernel<<<SEQ, 256>>>(h2, ln2, h3a2);

    cudaStreamWaitEvent(0, g_aux.evGU, 0);
    hgemm_kernel<<<dim3(SEQ/128, NGU/128), 256, HG_SMEM>>>(
        h3a2, Wgu2, nullptr, nullptr, nullptr, NGU, NGU, nullptr, gu, NGU, HID);

    siluconv_kernel<<<dim3(INTER/256, SEQ), 256>>>(gu, gt2);

    cudaStreamWaitEvent(0, g_aux.evWd, 0);
    hgemm_kernel<<<dim3(SEQ/128, HID/128), 256, HG_SMEM>>>(
        gt2, Wd2, nullptr, nullptr, nullptr, HID, HID, h2, out, HID, INTER);
}